// round 1
// baseline (speedup 1.0000x reference)
#include <cuda_runtime.h>

// Problem constants
#define BATCH 1024
#define CIN   3
#define FF    16
#define SS    28
// float4 elements: 1024*3*16*28*(28/4)
#define TOTAL4 (BATCH*3*FF*SS*(SS/4))

// Effective affine map: out[b,co,d,h,w] = sum_i E[co,i,fd,fh,fw]*x[b,i] + B[co,fd,fh,fw]
// fd/fh/fw are 5-valued boundary classes per dimension.
__device__ float g_E[3 * 3 * 5 * 5 * 5];   // 1125
__device__ float g_B[3 * 5 * 5 * 5];       // 375

__device__ __forceinline__ int fcls(int p, int n) {
    if (p == 0)     return 0;
    if (p == 1)     return 1;
    if (p == n - 1) return 4;
    if (p == n - 2) return 3;
    return 2;
}

// ---------------------------------------------------------------------------
// Precompute E and Beff from conv weights. One block, ~microseconds.
// ---------------------------------------------------------------------------
__global__ void precompute_kernel(const float* __restrict__ w1, const float* __restrict__ b1,
                                  const float* __restrict__ w2, const float* __restrict__ b2) {
    // S1[o][i][cd][ch][cw]: conv1 tap-sum for 3-valued boundary class per dim.
    // class 0 (p==0): taps {1,2}; class 1: all; class 2 (p==n-1): taps {0,1}
    __shared__ float S1[4 * 3 * 27];
    int t = threadIdx.x;

    for (int e = t; e < 324; e += blockDim.x) {
        int cw = e % 3, ch = (e / 3) % 3, cd = (e / 9) % 3, i = (e / 27) % 3, o = e / 81;
        float s = 0.f;
        for (int kd = 0; kd < 3; kd++) {
            if ((cd == 0 && kd == 0) || (cd == 2 && kd == 2)) continue;
            for (int kh = 0; kh < 3; kh++) {
                if ((ch == 0 && kh == 0) || (ch == 2 && kh == 2)) continue;
                for (int kw = 0; kw < 3; kw++) {
                    if ((cw == 0 && kw == 0) || (cw == 2 && kw == 2)) continue;
                    s += w1[(((o * 3 + i) * 3 + kd) * 3 + kh) * 3 + kw];
                }
            }
        }
        S1[e] = s;
    }
    __syncthreads();

    // Per final class f (5 values) and tap index t (offset t-1):
    //   validf[f][t]  — is the tap inside the volume
    //   nbc[f][t]     — conv1 boundary class of the neighbor position
    const int validf[5][3] = {{0,1,1},{1,1,1},{1,1,1},{1,1,1},{1,1,0}};
    const int nbc[5][3]    = {{0,0,1},{0,1,1},{1,1,1},{1,1,2},{1,2,0}};

    // E[co][i][fd][fh][fw]
    for (int e = t; e < 1125; e += blockDim.x) {
        int fw = e % 5, fh = (e / 5) % 5, fd = (e / 25) % 5, i = (e / 125) % 3, co = e / 375;
        float s = 0.f;
        for (int o = 0; o < 4; o++) {
            for (int td = 0; td < 3; td++) {
                if (!validf[fd][td]) continue;
                int cd = nbc[fd][td];
                for (int th = 0; th < 3; th++) {
                    if (!validf[fh][th]) continue;
                    int ch = nbc[fh][th];
                    for (int tw = 0; tw < 3; tw++) {
                        if (!validf[fw][tw]) continue;
                        int cw = nbc[fw][tw];
                        s += w2[(((co * 4 + o) * 3 + td) * 3 + th) * 3 + tw]
                           * S1[(((o * 3 + i) * 3 + cd) * 3 + ch) * 3 + cw];
                    }
                }
            }
        }
        g_E[e] = s;
    }

    // Beff[co][fd][fh][fw] = b2[co] + sum_o b1[o] * (sum of valid w2 taps)
    for (int e = t; e < 375; e += blockDim.x) {
        int fw = e % 5, fh = (e / 5) % 5, fd = (e / 25) % 5, co = e / 125;
        float s = b2[co];
        for (int o = 0; o < 4; o++) {
            float ws = 0.f;
            for (int td = 0; td < 3; td++) {
                if (!validf[fd][td]) continue;
                for (int th = 0; th < 3; th++) {
                    if (!validf[fh][th]) continue;
                    for (int tw = 0; tw < 3; tw++) {
                        if (!validf[fw][tw]) continue;
                        ws += w2[(((co * 4 + o) * 3 + td) * 3 + th) * 3 + tw];
                    }
                }
            }
            s += b1[o] * ws;
        }
        g_B[e] = s;
    }
}

// ---------------------------------------------------------------------------
// Main kernel: pure streaming fill. One float4 (4 consecutive w) per thread.
// Store-bound by construction; tables stay hot in L1 via __ldg.
// ---------------------------------------------------------------------------
__global__ void __launch_bounds__(256) expand_kernel(const float* __restrict__ x,
                                                     float4* __restrict__ out) {
    int idx = blockIdx.x * blockDim.x + threadIdx.x;
    if (idx >= TOTAL4) return;

    int w4 = idx % 7;
    int r  = idx / 7;
    int h  = r % SS; r /= SS;
    int d  = r % FF; r /= FF;
    int co = r % 3;
    int b  = r / 3;

    float x0 = __ldg(&x[b * 3 + 0]);
    float x1 = __ldg(&x[b * 3 + 1]);
    float x2 = __ldg(&x[b * 3 + 2]);

    int fd = fcls(d, FF);
    int fh = fcls(h, SS);
    int baseE = co * 375 + fd * 25 + fh * 5;   // i stride = 125
    int baseB = co * 125 + fd * 25 + fh * 5;

    float4 o4;
    float* op = reinterpret_cast<float*>(&o4);
#pragma unroll
    for (int j = 0; j < 4; j++) {
        int w  = w4 * 4 + j;
        int fw = fcls(w, SS);
        op[j] = __ldg(&g_B[baseB + fw])
              + x0 * __ldg(&g_E[baseE + fw])
              + x1 * __ldg(&g_E[baseE + 125 + fw])
              + x2 * __ldg(&g_E[baseE + 250 + fw]);
    }
    // Streaming store: output is write-once, never re-read.
    __stcs(&out[idx], o4);
}

extern "C" void kernel_launch(void* const* d_in, const int* in_sizes, int n_in,
                              void* d_out, int out_size) {
    const float* x  = (const float*)d_in[0];
    const float* w1 = (const float*)d_in[1];
    const float* b1 = (const float*)d_in[2];
    const float* w2 = (const float*)d_in[3];
    const float* b2 = (const float*)d_in[4];

    precompute_kernel<<<1, 1024>>>(w1, b1, w2, b2);

    const int total4 = TOTAL4;
    expand_kernel<<<(total4 + 255) / 256, 256>>>(x, (float4*)d_out);
}

// round 3
// speedup vs baseline: 1.4986x; 1.4986x over previous
#include <cuda_runtime.h>

#define FF 16
#define SS 28
#define B_ 1024

// Effective affine map: out[b,co,d,h,w] = sum_i E[co,i,fd,fh,fw]*x[b,i] + B[co,fd,fh,fw]
// fd/fh/fw are 5-valued boundary classes per dimension.
__device__ float g_E[3 * 3 * 5 * 5 * 5];   // 1125
__device__ float g_B[3 * 5 * 5 * 5];       // 375

__device__ __forceinline__ int fcls(int p, int n) {
    int c = 2;
    if (p == 0)          c = 0;
    else if (p == 1)     c = 1;
    else if (p == n - 1) c = 4;
    else if (p == n - 2) c = 3;
    return c;
}

// ---------------------------------------------------------------------------
// Precompute E and Beff from conv weights. One block; weights staged in smem
// so global-load latency is paid once (coalesced), not per-term.
// ---------------------------------------------------------------------------
__global__ void precompute_kernel(const float* __restrict__ w1, const float* __restrict__ b1,
                                  const float* __restrict__ w2, const float* __restrict__ b2) {
    __shared__ float sw1[324], sw2[324], S1[324];
    __shared__ float sb1[4], sb2[3];
    int t = threadIdx.x;

    if (t < 324) { sw1[t] = w1[t]; sw2[t] = w2[t]; }
    if (t < 4) sb1[t] = b1[t];
    if (t < 3) sb2[t] = b2[t];
    __syncthreads();

    // S1[o][i][cd][ch][cw]: conv1 tap-sum for 3-valued boundary class per dim.
    for (int e = t; e < 324; e += blockDim.x) {
        int cw = e % 3, ch = (e / 3) % 3, cd = (e / 9) % 3;
        int base = (e / 27) * 27;   // (o*3+i)*27
        float s = 0.f;
        for (int kd = 0; kd < 3; kd++) {
            if ((cd == 0 && kd == 0) || (cd == 2 && kd == 2)) continue;
            for (int kh = 0; kh < 3; kh++) {
                if ((ch == 0 && kh == 0) || (ch == 2 && kh == 2)) continue;
                for (int kw = 0; kw < 3; kw++) {
                    if ((cw == 0 && kw == 0) || (cw == 2 && kw == 2)) continue;
                    s += sw1[base + kd * 9 + kh * 3 + kw];
                }
            }
        }
        S1[e] = s;
    }
    __syncthreads();

    const int validf[5][3] = {{0,1,1},{1,1,1},{1,1,1},{1,1,1},{1,1,0}};
    const int nbc[5][3]    = {{0,0,1},{0,1,1},{1,1,1},{1,1,2},{1,2,0}};

    // E[co][i][fd][fh][fw]
    for (int e = t; e < 1125; e += blockDim.x) {
        int fw = e % 5, fh = (e / 5) % 5, fd = (e / 25) % 5, i = (e / 125) % 3, co = e / 375;
        float s = 0.f;
        for (int o = 0; o < 4; o++) {
            for (int td = 0; td < 3; td++) {
                if (!validf[fd][td]) continue;
                int cd = nbc[fd][td];
                for (int th = 0; th < 3; th++) {
                    if (!validf[fh][th]) continue;
                    int ch = nbc[fh][th];
                    for (int tw = 0; tw < 3; tw++) {
                        if (!validf[fw][tw]) continue;
                        int cw = nbc[fw][tw];
                        s += sw2[(((co * 4 + o) * 3 + td) * 3 + th) * 3 + tw]
                           * S1[(((o * 3 + i) * 3 + cd) * 3 + ch) * 3 + cw];
                    }
                }
            }
        }
        g_E[e] = s;
    }

    // Beff[co][fd][fh][fw] = b2[co] + sum_o b1[o] * (sum of valid w2 taps)
    for (int e = t; e < 375; e += blockDim.x) {
        int fw = e % 5, fh = (e / 5) % 5, fd = (e / 25) % 5, co = e / 125;
        float s = sb2[co];
        for (int o = 0; o < 4; o++) {
            float ws = 0.f;
            for (int td = 0; td < 3; td++) {
                if (!validf[fd][td]) continue;
                for (int th = 0; th < 3; th++) {
                    if (!validf[fh][th]) continue;
                    for (int tw = 0; tw < 3; tw++) {
                        if (!validf[fw][tw]) continue;
                        ws += sw2[(((co * 4 + o) * 3 + td) * 3 + th) * 3 + tw];
                    }
                }
            }
            s += sb1[o] * ws;
        }
        g_B[e] = s;
    }
}

// ---------------------------------------------------------------------------
// Expand: one block per batch element b. Build the full 375-entry value table
// v[co][fd][fh][fw] once (every distinct output value of this batch element),
// then 196 threads stream all 3*16*196 float4s: per store just 4 LDS + STG.128
// with indices constant-folded by the unrolled d-loop.
// Output float4 index = ((b*3 + co)*16 + d)*196 + tid, tid = h*7 + w4.
// ---------------------------------------------------------------------------
__global__ void __launch_bounds__(224) expand_kernel(const float* __restrict__ x,
                                                     float4* __restrict__ out) {
    __shared__ float v[375];           // v[co*125 + fd*25 + fh*5 + fw]
    const int b   = blockIdx.x;
    const int tid = threadIdx.x;

    // Build the table: 375 values, <=2 per thread.
    float x0 = __ldg(&x[b * 3 + 0]);
    float x1 = __ldg(&x[b * 3 + 1]);
    float x2 = __ldg(&x[b * 3 + 2]);
    for (int e = tid; e < 375; e += 224) {
        int co = e / 125;
        int sp = e - co * 125;         // fd*25 + fh*5 + fw
        int eb = co * 375 + sp;        // i stride = 125 in g_E
        v[e] = g_B[e] + x0 * g_E[eb] + x1 * g_E[eb + 125] + x2 * g_E[eb + 250];
    }
    __syncthreads();

    if (tid < 196) {
        int h  = tid / 7;
        int w4 = tid - h * 7;
        int fh = fcls(h, SS);
        // float4 lane -> fw class: w4==0:(0,1,2,2)  w4==6:(2,2,3,4)  else 2x4
        int i0 = (w4 == 0) ? 0 : 2;
        int i1 = (w4 == 0) ? 1 : 2;
        int i2 = (w4 == 6) ? 3 : 2;
        int i3 = (w4 == 6) ? 4 : 2;
        int base = fh * 5;             // + co*125 + fd*25

        // d -> class table, constant so the unrolled loop folds it away.
        const int dcls[FF] = {0,1,2,2,2,2,2,2,2,2,2,2,2,2,3,4};

        float4* op = out + (size_t)b * (3 * FF * 196) + tid;
#pragma unroll
        for (int co = 0; co < 3; co++) {
#pragma unroll
            for (int d = 0; d < FF; d++) {
                const float* vv = v + co * 125 + dcls[d] * 25 + base;
                float4 o4 = make_float4(vv[i0], vv[i1], vv[i2], vv[i3]);
                __stcs(op + (co * FF + d) * 196, o4);
            }
        }
    }
}

extern "C" void kernel_launch(void* const* d_in, const int* in_sizes, int n_in,
                              void* d_out, int out_size) {
    const float* x  = (const float*)d_in[0];
    const float* w1 = (const float*)d_in[1];
    const float* b1 = (const float*)d_in[2];
    const float* w2 = (const float*)d_in[3];
    const float* b2 = (const float*)d_in[4];

    precompute_kernel<<<1, 512>>>(w1, b1, w2, b2);
    expand_kernel<<<B_, 224>>>(x, (float4*)d_out);
}

// round 5
// speedup vs baseline: 2.1376x; 1.4264x over previous
#include <cuda_runtime.h>

#define FF 16
#define SS 28
#define B_ 1024

// Effective affine map: out[b,co,d,h,w] = sum_i E[co,i,fd,fh,fw]*x[b,i] + B[co,fd,fh,fw]
// fd/fh/fw are 5-valued boundary classes per dimension.
__device__ float g_E[3 * 3 * 5 * 5 * 5];   // 1125
__device__ float g_B[3 * 5 * 5 * 5];       // 375

__device__ __forceinline__ int fcls(int p, int n) {
    int c = 2;
    if (p == 0)          c = 0;
    else if (p == 1)     c = 1;
    else if (p == n - 1) c = 4;
    else if (p == n - 2) c = 3;
    return c;
}

// ---------------------------------------------------------------------------
// Precompute E and Beff. 9 blocks x 160 threads: each block redundantly builds
// S1 (cheap), then computes a 125-element slice of E with ONE element per
// thread. Blocks 0-2 also cover B (one entry per thread).
// NOTE: all smem staging uses strided LOOPS (blockDim < 324!).
// ---------------------------------------------------------------------------
__global__ void __launch_bounds__(160) precompute_kernel(
        const float* __restrict__ w1, const float* __restrict__ b1,
        const float* __restrict__ w2, const float* __restrict__ b2) {
    __shared__ float sw1[324], sw2[324], S1[324];
    __shared__ float sb1[4], sb2[3];
    const int t   = threadIdx.x;
    const int blk = blockIdx.x;

    for (int e = t; e < 324; e += 160) { sw1[e] = w1[e]; sw2[e] = w2[e]; }
    if (t < 4) sb1[t] = b1[t];
    if (t < 3) sb2[t] = b2[t];
    __syncthreads();

    // S1[o][i][cd][ch][cw]: conv1 tap-sum per 3-valued boundary class per dim.
    for (int e = t; e < 324; e += 160) {
        int cw = e % 3, ch = (e / 3) % 3, cd = (e / 9) % 3;
        int base = (e / 27) * 27;
        float s = 0.f;
#pragma unroll
        for (int kd = 0; kd < 3; kd++) {
            if ((cd == 0 && kd == 0) || (cd == 2 && kd == 2)) continue;
#pragma unroll
            for (int kh = 0; kh < 3; kh++) {
                if ((ch == 0 && kh == 0) || (ch == 2 && kh == 2)) continue;
#pragma unroll
                for (int kw = 0; kw < 3; kw++) {
                    if ((cw == 0 && kw == 0) || (cw == 2 && kw == 2)) continue;
                    s += sw1[base + kd * 9 + kh * 3 + kw];
                }
            }
        }
        S1[e] = s;
    }
    __syncthreads();

    const int validf[5][3] = {{0,1,1},{1,1,1},{1,1,1},{1,1,1},{1,1,0}};
    const int nbc[5][3]    = {{0,0,1},{0,1,1},{1,1,1},{1,1,2},{1,2,0}};

    // E slice: block blk owns elements [blk*125, blk*125+125), one per thread.
    if (t < 125) {
        int e  = blk * 125 + t;
        int fw = e % 5, fh = (e / 5) % 5, fd = (e / 25) % 5, i = (e / 125) % 3, co = e / 375;
        float s = 0.f;
        for (int o = 0; o < 4; o++) {
#pragma unroll
            for (int td = 0; td < 3; td++) {
                if (!validf[fd][td]) continue;
                int cd = nbc[fd][td];
#pragma unroll
                for (int th = 0; th < 3; th++) {
                    if (!validf[fh][th]) continue;
                    int ch = nbc[fh][th];
#pragma unroll
                    for (int tw = 0; tw < 3; tw++) {
                        if (!validf[fw][tw]) continue;
                        int cw = nbc[fw][tw];
                        s += sw2[(((co * 4 + o) * 3 + td) * 3 + th) * 3 + tw]
                           * S1[(((o * 3 + i) * 3 + cd) * 3 + ch) * 3 + cw];
                    }
                }
            }
        }
        g_E[e] = s;
    }

    // B: blocks 0-2, one entry per thread (t < 125).
    if (blk < 3 && t < 125) {
        int e  = blk * 125 + t;
        int fw = e % 5, fh = (e / 5) % 5, fd = (e / 25) % 5, co = e / 125;
        float s = sb2[co];
        for (int o = 0; o < 4; o++) {
            float ws = 0.f;
#pragma unroll
            for (int td = 0; td < 3; td++) {
                if (!validf[fd][td]) continue;
#pragma unroll
                for (int th = 0; th < 3; th++) {
                    if (!validf[fh][th]) continue;
#pragma unroll
                    for (int tw = 0; tw < 3; tw++) {
                        if (!validf[fw][tw]) continue;
                        ws += sw2[(((co * 4 + o) * 3 + td) * 3 + th) * 3 + tw];
                    }
                }
            }
            s += sb1[o] * ws;
        }
        g_B[e] = s;
    }
}

// ---------------------------------------------------------------------------
// Expand: 2 blocks per batch element (d 0-7 / 8-15) for smoother waves.
// Each block builds the full 375-entry value table v[co][fd][fh][fw] in smem,
// then 196 threads stream 3*8*196 float4s: 4 LDS + 1 STG.128 each, indices
// constant-folded by the unrolled loops.
// ---------------------------------------------------------------------------
__global__ void __launch_bounds__(224) expand_kernel(const float* __restrict__ x,
                                                     float4* __restrict__ out) {
    __shared__ float v[375];           // v[co*125 + fd*25 + fh*5 + fw]
    const int blk = blockIdx.x;
    const int b   = blk >> 1;
    const int p   = blk & 1;           // d-half: 0 -> d 0..7, 1 -> d 8..15
    const int tid = threadIdx.x;

    float x0 = __ldg(&x[b * 3 + 0]);
    float x1 = __ldg(&x[b * 3 + 1]);
    float x2 = __ldg(&x[b * 3 + 2]);
    for (int e = tid; e < 375; e += 224) {
        int co = e / 125;
        int sp = e - co * 125;
        int eb = co * 375 + sp;        // i stride = 125 in g_E
        v[e] = g_B[e] + x0 * g_E[eb] + x1 * g_E[eb + 125] + x2 * g_E[eb + 250];
    }
    __syncthreads();

    if (tid < 196) {
        int h  = tid / 7;
        int w4 = tid - h * 7;
        int fh = fcls(h, SS);
        // float4 lane -> fw class: w4==0:(0,1,2,2)  w4==6:(2,2,3,4)  else 2x4
        int i0 = (w4 == 0) ? 0 : 2;
        int i1 = (w4 == 0) ? 1 : 2;
        int i2 = (w4 == 6) ? 3 : 2;
        int i3 = (w4 == 6) ? 4 : 2;
        int base = fh * 5;

        // d -> class, for this half; constant tables fold under unroll.
        const int dcls0[8] = {0,1,2,2,2,2,2,2};
        const int dcls1[8] = {2,2,2,2,2,2,3,4};

        float4* op = out + (size_t)b * (3 * FF * 196) + (size_t)p * (8 * 196) + tid;
#pragma unroll
        for (int co = 0; co < 3; co++) {
#pragma unroll
            for (int dd = 0; dd < 8; dd++) {
                int fd = p ? dcls1[dd] : dcls0[dd];
                const float* vv = v + co * 125 + fd * 25 + base;
                float4 o4 = make_float4(vv[i0], vv[i1], vv[i2], vv[i3]);
                __stcs(op + (co * FF + dd) * 196, o4);
            }
        }
    }
}

extern "C" void kernel_launch(void* const* d_in, const int* in_sizes, int n_in,
                              void* d_out, int out_size) {
    const float* x  = (const float*)d_in[0];
    const float* w1 = (const float*)d_in[1];
    const float* b1 = (const float*)d_in[2];
    const float* w2 = (const float*)d_in[3];
    const float* b2 = (const float*)d_in[4];

    precompute_kernel<<<9, 160>>>(w1, b1, w2, b2);
    expand_kernel<<<B_ * 2, 224>>>(x, (float4*)d_out);
}

// round 6
// speedup vs baseline: 2.6447x; 1.2372x over previous
#include <cuda_runtime.h>

#define FF 16
#define SS 28
#define B_ 1024

// Effective affine map: out[b,co,d,h,w] = sum_i E[co,i,fd,fh,fw]*x[b,i] + B[co,fd,fh,fw]
__device__ float g_E[3 * 3 * 5 * 5 * 5];   // 1125
__device__ float g_B[3 * 5 * 5 * 5];       // 375

__device__ __forceinline__ int fcls(int p, int n) {
    int c = 2;
    if (p == 0)          c = 0;
    else if (p == 1)     c = 1;
    else if (p == n - 1) c = 4;
    else if (p == n - 2) c = 3;
    return c;
}

// conv1 3-class mask: class 0 drops tap k=0, class 2 drops tap k=2.
__device__ __forceinline__ float mask3(int c, int k) {
    return ((c == 0 && k == 0) || (c == 2 && k == 2)) ? 0.f : 1.f;
}

// ---------------------------------------------------------------------------
// Precompute E and Beff — BRANCH-FREE. 9 blocks x 128 threads.
// All class tables replaced by closed forms so nothing lands in local memory:
//   valid(f,t) = !((f==0 && t==0) || (f==4 && t==2))
//   nbc(f,t)   = cls3(f+t-1),  cls3(v) = (v==0) ? 0 : (v==4) ? 2 : 1
// Inner 108-term loop is fully unrolled straight-line FMA/LDS.
// ---------------------------------------------------------------------------
__global__ void __launch_bounds__(128) precompute_kernel(
        const float* __restrict__ w1, const float* __restrict__ b1,
        const float* __restrict__ w2, const float* __restrict__ b2) {
    __shared__ float sw1[324], sw2[324], S1[324];
    __shared__ float sb1[4], sb2[3];
    const int t   = threadIdx.x;
    const int blk = blockIdx.x;

    for (int e = t; e < 324; e += 128) { sw1[e] = w1[e]; sw2[e] = w2[e]; }
    if (t < 4) sb1[t] = b1[t];
    if (t < 3) sb2[t] = b2[t];
    __syncthreads();

    // S1[o][i][cd][ch][cw] = masked tap-sum of w1. Branch-free.
    for (int e = t; e < 324; e += 128) {
        int cw = e % 3, ch = (e / 3) % 3, cd = (e / 9) % 3;
        int base = (e / 27) * 27;
        float s = 0.f;
#pragma unroll
        for (int kd = 0; kd < 3; kd++) {
            float md = mask3(cd, kd);
#pragma unroll
            for (int kh = 0; kh < 3; kh++) {
                float mh = md * mask3(ch, kh);
#pragma unroll
                for (int kw = 0; kw < 3; kw++) {
                    s += mh * mask3(cw, kw) * sw1[base + kd * 9 + kh * 3 + kw];
                }
            }
        }
        S1[e] = s;
    }
    __syncthreads();

    if (t < 125) {
        const int fw = t % 5, fh = (t / 5) % 5, fd = t / 25;

        // Per-dim validity (float 0/1) and neighbor class, in registers.
        float vaD[3], vaH[3], vaW[3];
        int   nbD[3], nbH[3], nbW[3];
#pragma unroll
        for (int tt = 0; tt < 3; tt++) {
            vaD[tt] = ((fd == 0 && tt == 0) || (fd == 4 && tt == 2)) ? 0.f : 1.f;
            vaH[tt] = ((fh == 0 && tt == 0) || (fh == 4 && tt == 2)) ? 0.f : 1.f;
            vaW[tt] = ((fw == 0 && tt == 0) || (fw == 4 && tt == 2)) ? 0.f : 1.f;
            int pd = fd + tt - 1; nbD[tt] = (pd == 0) ? 0 : (pd == 4) ? 2 : 1;
            int ph = fh + tt - 1; nbH[tt] = (ph == 0) ? 0 : (ph == 4) ? 2 : 1;
            int pw = fw + tt - 1; nbW[tt] = (pw == 0) ? 0 : (pw == 4) ? 2 : 1;
        }

        // --- E slice: element e = blk*125 + t;  i = blk%3, co = blk/3 ---
        {
            const int i  = blk % 3;
            const int co = blk / 3;
            float s = 0.f;
#pragma unroll
            for (int td = 0; td < 3; td++) {
                float cD = vaD[td]; int cd9 = nbD[td] * 9;
#pragma unroll
                for (int th = 0; th < 3; th++) {
                    float cH = cD * vaH[th]; int ch3 = cd9 + nbH[th] * 3;
#pragma unroll
                    for (int tw = 0; tw < 3; tw++) {
                        float coef = cH * vaW[tw];
                        int w2i = co * 108 + td * 9 + th * 3 + tw;   // + o*27
                        int s1i = i * 27 + ch3 + nbW[tw];            // + o*81
#pragma unroll
                        for (int o = 0; o < 4; o++)
                            s += coef * sw2[w2i + o * 27] * S1[s1i + o * 81];
                    }
                }
            }
            g_E[blk * 125 + t] = s;
        }

        // --- B: blocks 0-2 own co = blk ---
        if (blk < 3) {
            const int co = blk;
            float s = sb2[co];
#pragma unroll
            for (int o = 0; o < 4; o++) {
                float ws = 0.f;
#pragma unroll
                for (int td = 0; td < 3; td++) {
#pragma unroll
                    for (int th = 0; th < 3; th++) {
                        float cH = vaD[td] * vaH[th];
#pragma unroll
                        for (int tw = 0; tw < 3; tw++)
                            ws += cH * vaW[tw] * sw2[co * 108 + o * 27 + td * 9 + th * 3 + tw];
                    }
                }
                s += sb1[o] * ws;
            }
            g_B[blk * 125 + t] = s;
        }
    }
}

// ---------------------------------------------------------------------------
// Expand: 2 blocks per batch element (d 0-7 / 8-15). Each block builds the
// full 375-entry value table v[co][fd][fh][fw] in smem, then 196 threads
// stream 3*8*196 float4s: 4 LDS + 1 STG.128 each.  (Unchanged — at the
// HBM-write floor: ~5.8 TB/s effective.)
// ---------------------------------------------------------------------------
__global__ void __launch_bounds__(224) expand_kernel(const float* __restrict__ x,
                                                     float4* __restrict__ out) {
    __shared__ float v[375];           // v[co*125 + fd*25 + fh*5 + fw]
    const int blk = blockIdx.x;
    const int b   = blk >> 1;
    const int p   = blk & 1;           // d-half: 0 -> d 0..7, 1 -> d 8..15
    const int tid = threadIdx.x;

    float x0 = __ldg(&x[b * 3 + 0]);
    float x1 = __ldg(&x[b * 3 + 1]);
    float x2 = __ldg(&x[b * 3 + 2]);
    for (int e = tid; e < 375; e += 224) {
        int co = e / 125;
        int sp = e - co * 125;
        int eb = co * 375 + sp;        // i stride = 125 in g_E
        v[e] = g_B[e] + x0 * g_E[eb] + x1 * g_E[eb + 125] + x2 * g_E[eb + 250];
    }
    __syncthreads();

    if (tid < 196) {
        int h  = tid / 7;
        int w4 = tid - h * 7;
        int fh = fcls(h, SS);
        int i0 = (w4 == 0) ? 0 : 2;
        int i1 = (w4 == 0) ? 1 : 2;
        int i2 = (w4 == 6) ? 3 : 2;
        int i3 = (w4 == 6) ? 4 : 2;
        int base = fh * 5;

        const int dcls0[8] = {0,1,2,2,2,2,2,2};
        const int dcls1[8] = {2,2,2,2,2,2,3,4};

        float4* op = out + (size_t)b * (3 * FF * 196) + (size_t)p * (8 * 196) + tid;
#pragma unroll
        for (int co = 0; co < 3; co++) {
#pragma unroll
            for (int dd = 0; dd < 8; dd++) {
                int fd = p ? dcls1[dd] : dcls0[dd];
                const float* vv = v + co * 125 + fd * 25 + base;
                float4 o4 = make_float4(vv[i0], vv[i1], vv[i2], vv[i3]);
                __stcs(op + (co * FF + dd) * 196, o4);
            }
        }
    }
}

extern "C" void kernel_launch(void* const* d_in, const int* in_sizes, int n_in,
                              void* d_out, int out_size) {
    const float* x  = (const float*)d_in[0];
    const float* w1 = (const float*)d_in[1];
    const float* b1 = (const float*)d_in[2];
    const float* w2 = (const float*)d_in[3];
    const float* b2 = (const float*)d_in[4];

    precompute_kernel<<<9, 128>>>(w1, b1, w2, b2);
    expand_kernel<<<B_ * 2, 224>>>(x, (float4*)d_out);
}